// round 1
// baseline (speedup 1.0000x reference)
#include <cuda_runtime.h>

#define Bc 64
#define Tc 2000
#define Lc 400
#define Mc 80
#define EPSc 1e-8f

// accumulators: 0=s1(mel1), 1=s2(mel2), 2=gate, 3=kl_sum, 4=ent_sum(Σ p*logp)
__device__ double g_acc[5];

__device__ __forceinline__ float warp_sum(float v) {
    v += __shfl_xor_sync(0xffffffffu, v, 16);
    v += __shfl_xor_sync(0xffffffffu, v, 8);
    v += __shfl_xor_sync(0xffffffffu, v, 4);
    v += __shfl_xor_sync(0xffffffffu, v, 2);
    v += __shfl_xor_sync(0xffffffffu, v, 1);
    return v;
}

__global__ void init_kernel() {
    if (threadIdx.x < 5) g_acc[threadIdx.x] = 0.0;
}

// ---------------- mel L1 losses ----------------
__global__ void mel_kernel(const float4* __restrict__ post,
                           const float4* __restrict__ out,
                           const float4* __restrict__ tgt,
                           const int* __restrict__ mel_len) {
    const int n4 = Bc * Tc * Mc / 4;  // 2,048,000
    float s1 = 0.f, s2 = 0.f;
    for (int i = blockIdx.x * blockDim.x + threadIdx.x; i < n4;
         i += gridDim.x * blockDim.x) {
        int row = i / (Mc / 4);
        int b = row / Tc;
        int t = row - b * Tc;
        if (t < __ldg(&mel_len[b])) {
            float4 o = out[i], p = post[i], g = tgt[i];
            s1 += fabsf(o.x - g.x) + fabsf(o.y - g.y) + fabsf(o.z - g.z) + fabsf(o.w - g.w);
            s2 += fabsf(p.x - g.x) + fabsf(p.y - g.y) + fabsf(p.z - g.z) + fabsf(p.w - g.w);
        }
    }
    __shared__ float sm1[8], sm2[8];
    int lane = threadIdx.x & 31, wid = threadIdx.x >> 5;
    s1 = warp_sum(s1);
    s2 = warp_sum(s2);
    if (lane == 0) { sm1[wid] = s1; sm2[wid] = s2; }
    __syncthreads();
    if (wid == 0) {
        float a = (lane < (blockDim.x >> 5)) ? sm1[lane] : 0.f;
        float b2 = (lane < (blockDim.x >> 5)) ? sm2[lane] : 0.f;
        a = warp_sum(a);
        b2 = warp_sum(b2);
        if (lane == 0) {
            atomicAdd(&g_acc[0], (double)a);
            atomicAdd(&g_acc[1], (double)b2);
        }
    }
}

// ---------------- gate BCE-with-logits ----------------
__global__ void gate_kernel(const float* __restrict__ x,
                            const float* __restrict__ z) {
    const int n = Bc * Tc;
    float s = 0.f;
    for (int i = blockIdx.x * blockDim.x + threadIdx.x; i < n;
         i += gridDim.x * blockDim.x) {
        float xi = x[i], zi = z[i];
        s += fmaxf(xi, 0.f) - xi * zi + log1pf(__expf(-fabsf(xi)));
    }
    __shared__ float sm[8];
    int lane = threadIdx.x & 31, wid = threadIdx.x >> 5;
    s = warp_sum(s);
    if (lane == 0) sm[wid] = s;
    __syncthreads();
    if (wid == 0) {
        float a = (lane < (blockDim.x >> 5)) ? sm[lane] : 0.f;
        a = warp_sum(a);
        if (lane == 0) atomicAdd(&g_acc[2], (double)a);
    }
}

// ---------------- attention KL + entropy (one warp per (b,t) row) -----------
// kl_row = sum_l t_l (log t_l - log p_l), t_l = g_l/S, g_l = exp(h_l), h_l = -z^2/2
// => kl_row = (A - sg*lnS)/S with A = sum g*(h - logp), S = sg + EPS
__global__ void attn_kernel(const float4* __restrict__ attn,
                            const int* __restrict__ text_len) {
    int gwarp = (blockIdx.x * blockDim.x + threadIdx.x) >> 5;
    int lane = threadIdx.x & 31;
    int b = gwarp / Tc;
    int t = gwarp - b * Tc;

    int Lb = __ldg(&text_len[b]);
    float sigma = fminf(fmaxf((float)Lb * 0.05f, 3.0f), 10.0f);
    float inv_sig = 1.0f / sigma;
    int ep_i = (t * Lb) / Tc;
    if (ep_i > Lb - 1) ep_i = Lb - 1;
    float ep = (float)ep_i;

    const float4* row = attn + (long long)gwarp * (Lc / 4);

    float sg = 0.f, A = 0.f, E = 0.f;
    for (int j = lane; j < Lc / 4; j += 32) {
        float4 a4 = row[j];
        int l0 = j * 4;
        float av[4] = {a4.x, a4.y, a4.z, a4.w};
#pragma unroll
        for (int k = 0; k < 4; k++) {
            float a = fmaxf(av[k], EPSc);
            float lp = __logf(a);
            E += a * lp;
            int l = l0 + k;
            if (l < Lb) {
                float zz = ((float)l - ep) * inv_sig;
                float h = -0.5f * zz * zz;
                float g = __expf(h);
                sg += g;
                A += g * (h - lp);
            }
        }
    }
    sg = warp_sum(sg);
    A = warp_sum(A);
    E = warp_sum(E);

    __shared__ float skl[8], sent[8];
    int wid = threadIdx.x >> 5;
    if (lane == 0) {
        float S = sg + EPSc;
        float lnS = __logf(S);
        skl[wid] = (A - sg * lnS) / S;
        sent[wid] = E;
    }
    __syncthreads();
    if (wid == 0) {
        int nw = blockDim.x >> 5;
        float kl = (lane < nw) ? skl[lane] : 0.f;
        float en = (lane < nw) ? sent[lane] : 0.f;
        kl = warp_sum(kl);
        en = warp_sum(en);
        if (lane == 0) {
            atomicAdd(&g_acc[3], (double)kl);
            atomicAdd(&g_acc[4], (double)en);
        }
    }
}

// ---------------- finalize ----------------
__global__ void final_kernel(const int* __restrict__ mel_len,
                             float* __restrict__ out) {
    if (threadIdx.x == 0 && blockIdx.x == 0) {
        double nvalid = 0.0;
        for (int b = 0; b < Bc; b++) nvalid += (double)mel_len[b];
        nvalid *= (double)Mc;

        double loss_mel = (g_acc[0] + g_acc[1]) / nvalid;
        double loss_gate = g_acc[2] / (double)(Bc * Tc);
        double kl = g_acc[3] / (double)Bc / (double)Tc;
        if (kl > 150.0) kl = 150.0;
        double ent = -g_acc[4] / (double)(Bc * Tc);
        double ratio = ent / 3.5;
        if (ratio < 0.0) ratio = 0.0;
        double w;
        if (ent <= 3.5) {
            w = ratio > 0.2 ? ratio : 0.2;
        } else {
            w = 1.0;
        }
        double total = loss_mel + loss_gate + w * kl;
        out[0] = (float)total;
        out[1] = (float)loss_mel;
        out[2] = (float)loss_gate;
        out[3] = (float)kl;
    }
}

extern "C" void kernel_launch(void* const* d_in, const int* in_sizes, int n_in,
                              void* d_out, int out_size) {
    const float* mel_out_postnet = (const float*)d_in[0];
    const float* mel_out         = (const float*)d_in[1];
    const float* gate_out        = (const float*)d_in[2];
    const float* alignments      = (const float*)d_in[3];
    const float* mel_target      = (const float*)d_in[4];
    const float* gate_target     = (const float*)d_in[5];
    const int*   mel_lengths     = (const int*)d_in[6];
    const int*   text_lengths    = (const int*)d_in[7];
    float* out = (float*)d_out;

    init_kernel<<<1, 32>>>();
    mel_kernel<<<2368, 256>>>((const float4*)mel_out_postnet,
                              (const float4*)mel_out,
                              (const float4*)mel_target, mel_lengths);
    gate_kernel<<<128, 256>>>(gate_out, gate_target);
    // one warp per (b,t) row: 128000 rows / 8 warps per block
    attn_kernel<<<(Bc * Tc) / 8, 256>>>((const float4*)alignments, text_lengths);
    final_kernel<<<1, 32>>>(mel_lengths, out);
    (void)in_sizes; (void)n_in; (void)out_size;
}